// round 17
// baseline (speedup 1.0000x reference)
#include <cuda_runtime.h>
#include <cstdint>

// ForwardKinematics: B=262144 hand FK chains.
// LOCKED rounding model (R11..R16 PASS, rel_err 3.508e-9):
//  - sin/cos: glibc scalar sinf/cosf semantics; fast path = exact double
//    reduction + compensated f32-pair (EFT) Horner polys (~2^-46), DP
//    fallback for boundary/large inputs.
//  - rot compose + chain einsum dots: fma(a2,b2, fma(a1,b1, a0*b0))
//  - elementwise (p + bone*Rcol, pos*irbl + root): separate mul/add
//  - projection einsum dot: separate mul/add left-assoc; __fdiv_rn
// This round (latency-bound @ occ 23.5%, issue 20%): occupancy push with
// ZERO arithmetic change — lazy operand loads (drop oa[23]/bl[20] resident
// arrays) + __launch_bounds__(256,3) -> 3 blocks/SM, 37.5% occupancy.

#define FMUL(a, b) __fmul_rn((a), (b))
#define FADD(a, b) __fadd_rn((a), (b))
#define FMA3(a, b, c) __fmaf_rn((a), (b), (c))

// ---------------- glibc sincosf constants ----------------
#define GS_HPI_INV 0x1.45F306DC9C883p-1   // 2/pi (double)
#define GS_HPI     0x1.921FB54442D18p0    // pi/2
#define GS_C0  0x1p0
#define GS_C1 -0x1.ffffffd0c621cp-2
#define GS_C2  0x1.55553e1068f19p-5
#define GS_C3 -0x1.6c087e89a359dp-10
#define GS_C4  0x1.99343027bf8c3p-16
#define GS_S1 -0x1.555545995a603p-3
#define GS_S2  0x1.1107605230bc4p-7
#define GS_S3 -0x1.994eb3774cf24p-13

#define SPLIT_HI(d) ((float)(d))
#define SPLIT_LO(d) ((float)((d) - (double)(float)(d)))

// ---------------- full-DP fallback (bit-exact glibc) ----------------
__device__ __noinline__ void dp_sincosf(float y, int n, float& so, float& co) {
    double x = (double)y;
    double rn = (double)n;
    double xr = __fma_rn(-rn, GS_HPI, x);
    double x2 = xr * xr;

    long long flip = (long long)(((n + 1) >> 1) & 1) << 63;
    double xs = __longlong_as_double(__double_as_longlong(xr) ^ flip);
    double x3 = xs * x2;
    double s1 = __fma_rn(x2, GS_S3, GS_S2);
    double x7 = x3 * x2;
    double ss = __fma_rn(x3, GS_S1, xs);
    float sine_res = (float)__fma_rn(x7, s1, ss);

    double x4  = x2 * x2;
    double cc2 = __fma_rn(x2, GS_C4, GS_C3);
    double cc1 = __fma_rn(x2, GS_C1, GS_C0);
    double x6  = x4 * x2;
    double cc  = __fma_rn(x4, GS_C2, cc1);
    float cos_res = (float)__fma_rn(x6, cc2, cc);
    cos_res = __uint_as_float(__float_as_uint(cos_res) ^ ((uint32_t)(n & 2) << 30));

    if (n & 1) { so = cos_res; co = sine_res; }
    else       { so = sine_res; co = cos_res; }
}

// ---------------- f32-pair (EFT) fast path ----------------
struct ff { float hi, err; };

__device__ __forceinline__ ff horner_step(ff acc, float wh, float wl,
                                          float Ch, float Cl) {
    float p  = __fmul_rn(acc.hi, wh);
    float e1 = __fmaf_rn(acc.hi, wh, -p);
    float s  = __fadd_rn(p, Ch);
    float bb = __fsub_rn(s, p);
    float e2 = __fadd_rn(__fsub_rn(p, __fsub_rn(s, bb)),
                         __fsub_rn(Ch, bb));
    float err = __fmaf_rn(acc.err, wh,
                 __fmaf_rn(acc.hi, wl,
                  __fadd_rn(__fadd_rn(e1, e2), Cl)));
    ff r; r.hi = s; r.err = err; return r;
}

__device__ __forceinline__ void fast_sincosf(float y, float& so, float& co) {
    const float INVPI_F = 0x1.45f306p-1f;
    float rf = __fmul_rn(y, INVPI_F);
    int n = __float2int_rn(rf);
    float resid = __fmaf_rn(y, INVPI_F, -(float)n);
    if (fabsf(resid) >= 0.4995f || fabsf(y) >= 30.0f) {
        double r = (double)y * GS_HPI_INV;
        dp_sincosf(y, (int)rint(r), so, co);
        return;
    }
    // glibc's exact double reduction (only DP-pipe work on fast path)
    double xr = __fma_rn(-(double)n, GS_HPI, (double)y);
    float xh = (float)xr;
    float xl = (float)(xr - (double)xh);

    float wh = __fmul_rn(xh, xh);
    float we = __fmaf_rn(xh, xh, -wh);
    float wl = __fmaf_rn(__fadd_rn(xh, xh), xl, we);

    ff P; P.hi = SPLIT_HI(GS_S3); P.err = SPLIT_LO(GS_S3);
    P = horner_step(P, wh, wl, SPLIT_HI(GS_S2), SPLIT_LO(GS_S2));
    P = horner_step(P, wh, wl, SPLIT_HI(GS_S1), SPLIT_LO(GS_S1));
    P = horner_step(P, wh, wl, 1.0f, 0.0f);

    uint32_t sflip = (uint32_t)(((n + 1) >> 1) & 1) << 31;
    float xsh = __uint_as_float(__float_as_uint(xh) ^ sflip);
    float xsl = __uint_as_float(__float_as_uint(xl) ^ sflip);
    float m  = __fmul_rn(xsh, P.hi);
    float em = __fmaf_rn(xsh, P.hi, -m);
    float slo = __fmaf_rn(xsh, P.err, __fmaf_rn(xsl, P.hi, em));
    float sine_res = __fadd_rn(m, slo);

    ff Q; Q.hi = SPLIT_HI(GS_C4); Q.err = SPLIT_LO(GS_C4);
    Q = horner_step(Q, wh, wl, SPLIT_HI(GS_C3), SPLIT_LO(GS_C3));
    Q = horner_step(Q, wh, wl, SPLIT_HI(GS_C2), SPLIT_LO(GS_C2));
    Q = horner_step(Q, wh, wl, SPLIT_HI(GS_C1), SPLIT_LO(GS_C1));
    Q = horner_step(Q, wh, wl, 1.0f, 0.0f);
    float cos_res = __fadd_rn(Q.hi, Q.err);
    cos_res = __uint_as_float(__float_as_uint(cos_res) ^ ((uint32_t)(n & 2) << 30));

    if (n & 1) { so = cos_res; co = sine_res; }
    else       { so = sine_res; co = cos_res; }
}

// ---------------- FK math (locked rounding) ----------------

__device__ __forceinline__ float dot3f(float a0, float b0, float a1, float b1,
                                       float a2, float b2) {
    return FMA3(a2, b2, FMA3(a1, b1, FMUL(a0, b0)));
}

__device__ __forceinline__ float dot3m(float a0, float b0, float a1, float b1,
                                       float a2, float b2) {
    return FADD(FADD(FMUL(a0, b0), FMUL(a1, b1)), FMUL(a2, b2));
}

__device__ __forceinline__ void mm3f(const float A[3][3], const float Bm[3][3],
                                     float C[3][3]) {
#pragma unroll
    for (int i = 0; i < 3; i++)
#pragma unroll
        for (int j = 0; j < 3; j++)
            C[i][j] = dot3f(A[i][0], Bm[0][j], A[i][1], Bm[1][j], A[i][2], Bm[2][j]);
}

__device__ __forceinline__ void rot_xyz(float sx, float cx, float sy, float cy,
                                        float sz, float cz, float L[3][3]) {
    float m10 = FMUL(sx, sy);
    float m12 = FMUL(-sx, cy);
    float m20 = FMUL(cx, -sy);
    float m22 = FMUL(cx, cy);
    L[0][0] = FMUL(cy, cz);
    L[0][1] = FMUL(cy, -sz);
    L[0][2] = sy;
    L[1][0] = FMA3(cx, sz, FMUL(m10, cz));
    L[1][1] = FMA3(cx, cz, FMUL(m10, -sz));
    L[1][2] = m12;
    L[2][0] = FMA3(sx, sz, FMUL(m20, cz));
    L[2][1] = FMA3(sx, cz, FMUL(m20, -sz));
    L[2][2] = m22;
}

__device__ __forceinline__ void rmul_full(float R[3][3], const float L[3][3]) {
    float T[3][3];
    mm3f(R, L, T);
#pragma unroll
    for (int i = 0; i < 3; i++)
#pragma unroll
        for (int j = 0; j < 3; j++) R[i][j] = T[i][j];
}

__device__ __forceinline__ void rmul_rx(float R[3][3], float s, float c) {
#pragma unroll
    for (int i = 0; i < 3; i++) {
        float a1 = R[i][1], a2 = R[i][2];
        R[i][1] = FMA3(a2, s, FMUL(a1, c));
        R[i][2] = FMA3(a2, c, FMUL(a1, -s));
    }
}

__device__ __forceinline__ void rmul_ry(float R[3][3], float s, float c) {
#pragma unroll
    for (int i = 0; i < 3; i++) {
        float a0 = R[i][0], a2 = R[i][2];
        R[i][0] = FMA3(a2, -s, FMUL(a0, c));
        R[i][2] = FMA3(a2, c, FMUL(a0, s));
    }
}

__device__ __forceinline__ void p_update(float p[3], const float R[3][3], float bone) {
#pragma unroll
    for (int i = 0; i < 3; i++) p[i] = FADD(p[i], FMUL(bone, R[i][2]));
}

__device__ __forceinline__ void emit_point(
    const float p[3], float irbl, const float root[3], const float K[3][3],
    float* __restrict__ out_abs, float* __restrict__ out_uv, int n) {
    float a[3];
#pragma unroll
    for (int i = 0; i < 3; i++) a[i] = FADD(FMUL(p[i], irbl), root[i]);
    out_abs[n * 3 + 0] = a[0];
    out_abs[n * 3 + 1] = a[1];
    out_abs[n * 3 + 2] = a[2];
    float q0 = dot3m(K[0][0], a[0], K[0][1], a[1], K[0][2], a[2]);
    float q1 = dot3m(K[1][0], a[0], K[1][1], a[1], K[1][2], a[2]);
    float q2 = dot3m(K[2][0], a[0], K[2][1], a[1], K[2][2], a[2]);
    float zr = (q2 == 0.0f) ? 1e-10f : q2;
    out_uv[n * 2 + 0] = __fdiv_rn(q0, zr);
    out_uv[n * 2 + 1] = __fdiv_rn(q1, zr);
}

__global__ __launch_bounds__(256, 3)
void fk_kernel(const float* __restrict__ root_angles,
               const float* __restrict__ other_angles,
               const float* __restrict__ bone_lengths,
               const float* __restrict__ cam,
               const float* __restrict__ irbl_in,
               const float* __restrict__ root_xyz,
               float* __restrict__ out_abs_base,
               float* __restrict__ out_uv_base,
               int B)
{
    int b = blockIdx.x * blockDim.x + threadIdx.x;
    if (b >= B) return;

    // operand base pointers — individual elements loaded lazily at use site
    const float* oa = other_angles + (size_t)b * 23;
    const float* bl = bone_lengths + (size_t)b * 20;

    float K[3][3];
#pragma unroll
    for (int i = 0; i < 3; i++)
#pragma unroll
        for (int j = 0; j < 3; j++) K[i][j] = cam[b * 9 + i * 3 + j];

    float irbl = irbl_in[b];
    float root[3];
#pragma unroll
    for (int i = 0; i < 3; i++) root[i] = root_xyz[b * 3 + i];

    float* out_abs = out_abs_base + (size_t)b * 63;
    float* out_uv  = out_uv_base  + (size_t)b * 42;

    // ---- root rotation ----
    float Rr[3][3];
    {
        float s0, c0, s1, c1, s2, c2;
        fast_sincosf(root_angles[b * 3 + 0], s0, c0);
        fast_sincosf(root_angles[b * 3 + 1], s1, c1);
        fast_sincosf(root_angles[b * 3 + 2], s2, c2);
        rot_xyz(s0, c0, s1, c1, s2, c2, Rr);
    }

    // keypoint 0 (wrist)
    {
        float p0[3] = {0.f, 0.f, 0.f};
        emit_point(p0, irbl, root, K, out_abs, out_uv, 0);
    }

    // Output keypoint index for finger f, level d: n = 1 + f*4 + (3 - d)
#pragma unroll
    for (int f = 0; f < 5; f++) {
        float R[3][3];
#pragma unroll
        for (int i = 0; i < 3; i++)
#pragma unroll
            for (int j = 0; j < 3; j++) R[i][j] = Rr[i][j];
        float p[3] = {0.f, 0.f, 0.f};
        float L[3][3];

        if (f == 0) {
            float s0, c0, s1, c1, s2, c2;
            fast_sincosf(oa[0], s0, c0);
            fast_sincosf(oa[1], s1, c1);
            fast_sincosf(oa[2], s2, c2);
            rot_xyz(s0, c0, s1, c1, s2, c2, L);
            rmul_full(R, L);
            p_update(p, R, bl[0]);
            emit_point(p, irbl, root, K, out_abs, out_uv, 1 + 3);

            fast_sincosf(oa[3], s0, c0);
            fast_sincosf(oa[4], s1, c1);
            fast_sincosf(oa[5], s2, c2);
            rot_xyz(s0, c0, s1, c1, s2, c2, L);
            rmul_full(R, L);
            p_update(p, R, bl[1]);
            emit_point(p, irbl, root, K, out_abs, out_uv, 1 + 2);

            fast_sincosf(oa[6], s0, c0);
            rmul_ry(R, s0, c0);
            p_update(p, R, bl[2]);
            emit_point(p, irbl, root, K, out_abs, out_uv, 1 + 1);

            p_update(p, R, bl[3]);
            emit_point(p, irbl, root, K, out_abs, out_uv, 1 + 0);
        } else {
            const int base = 7 + (f - 1) * 4;
            float s0, c0, s1, c1, s2, c2;

            fast_sincosf(oa[base + 0], s0, c0);
            fast_sincosf(oa[base + 1], s1, c1);
            rot_xyz(s0, c0, s1, c1, 0.f, 1.f, L);
            rmul_full(R, L);
            p_update(p, R, bl[f * 4 + 0]);
            emit_point(p, irbl, root, K, out_abs, out_uv, 1 + f * 4 + 3);

            fast_sincosf(oa[base + 2], s2, c2);
            rmul_rx(R, s2, c2);
            p_update(p, R, bl[f * 4 + 1]);
            emit_point(p, irbl, root, K, out_abs, out_uv, 1 + f * 4 + 2);

            fast_sincosf(oa[base + 3], s2, c2);
            rmul_rx(R, s2, c2);
            p_update(p, R, bl[f * 4 + 2]);
            emit_point(p, irbl, root, K, out_abs, out_uv, 1 + f * 4 + 1);

            p_update(p, R, bl[f * 4 + 3]);
            emit_point(p, irbl, root, K, out_abs, out_uv, 1 + f * 4 + 0);
        }
    }
}

extern "C" void kernel_launch(void* const* d_in, const int* in_sizes, int n_in,
                              void* d_out, int out_size)
{
    const float* root_angles  = (const float*)d_in[0];
    const float* other_angles = (const float*)d_in[1];
    const float* bone_lengths = (const float*)d_in[2];
    const float* cam          = (const float*)d_in[3];
    const float* irbl         = (const float*)d_in[4];
    const float* root_xyz     = (const float*)d_in[5];

    int B = in_sizes[0] / 3;

    float* out_abs = (float*)d_out;                   // (B,21,3)
    float* out_uv  = (float*)d_out + (size_t)B * 63;  // (B,21,2)

    int threads = 256;
    int blocks = (B + threads - 1) / threads;
    fk_kernel<<<blocks, threads>>>(root_angles, other_angles, bone_lengths,
                                   cam, irbl, root_xyz, out_abs, out_uv, B);
}